// round 11
// baseline (speedup 1.0000x reference)
#include <cuda_runtime.h>

// CRF negative log-likelihood, T=512 B=64 L=48, START=46, STOP=47.
// SINGLE-WARP per batch: lane q owns packed state pair (2q, 2q+1).
// Forward recursion in linear space, rescaled every RESC steps by u[0]:
//   v_pair[q] = (sum_i u_i * (E[i][2q], E[i][2q+1])) * (e_2q, e_2q+1) [* ru]
// u stored DUPLICATED in SMEM as (u_i, u_i) b64 -> consumer feeds packed
// FMAs directly from 24 broadcast LDS.128. No __syncthreads, no shfl on the
// step path: __syncwarp only. Accumulator stays packed to the store.

#define TT 512
#define BB 64
#define LLAB 48
#define START_TAG 46
#define STOP_TAG 47
#define NT 32
#define RESC 8
#define L2E 1.4426950408889634f
#define LN2f 0.6931471805599453f
#define FSTRIDE (BB * LLAB)   // 3072 floats per time step

__device__ float        g_partial[BB];
__device__ unsigned int g_done;       // wraps 0..63 -> self-resetting

__device__ __forceinline__ float ex2_approx(float x) {
    float r; asm("ex2.approx.ftz.f32 %0, %1;" : "=f"(r) : "f"(x)); return r;
}
__device__ __forceinline__ float lg2_approx(float x) {
    float r; asm("lg2.approx.ftz.f32 %0, %1;" : "=f"(r) : "f"(x)); return r;
}
__device__ __forceinline__ float rcp_approx(float x) {
    float r; asm("rcp.approx.ftz.f32 %0, %1;" : "=f"(r) : "f"(x)); return r;
}
__device__ __forceinline__ unsigned long long pk2(float lo, float hi) {
    unsigned long long p;
    asm("mov.b64 %0, {%1, %2};" : "=l"(p) : "f"(lo), "f"(hi)); return p;
}

__device__ __forceinline__ int get_tag(const void* tags, int idx, int is32) {
    int v = is32 ? ((const int*)tags)[idx]
                 : (int)((const long long*)tags)[idx];
    return v < 0 ? 0 : (v > 47 ? 47 : v);
}
__device__ __forceinline__ int get_mask(const void* mask, int idx, int is8) {
    return is8 ? (int)((const unsigned char*)mask)[idx]
               : (((const int*)mask)[idx] != 0);
}

__global__ __launch_bounds__(NT, 1) void crf_fused_kernel(
    const float* __restrict__ feats,      // (T, B, L)
    const float* __restrict__ trans,      // (L, L)
    const void*  __restrict__ candA,
    const void*  __restrict__ candB,
    float*       __restrict__ out)
{
    const int  b    = blockIdx.x;
    const int  lane = threadIdx.x;
    const bool act  = (lane < 24);
    const int  j0   = act ? 2 * lane : 0;   // this lane's packed state pair

    // s_ud[buf][i] = (u_i, u_i) duplicated b64
    __shared__ __align__(16) unsigned long long s_ud[2][LLAB];
    __shared__ int s_last;
    if (lane == 0) s_last = 0;

    // ---------------- buffer identification (shfl-OR, no atomics) ----------
    int flags = 0;
    {
        const unsigned* ua = (const unsigned*)candA;
        const unsigned* ub = (const unsigned*)candB;
        #pragma unroll
        for (int i = lane; i < 64; i += NT) {
            if (ua[i] & 0xFEFEFEFEu)  flags |= 1;   // A has byte>=2 -> A=tags
            if (ub[i] & 0xFEFEFEFEu)  flags |= 2;
            if (ua[2 * i + 1] != 0)   flags |= 4;   // odd words nonzero -> i32
            if (ub[2 * i + 1] != 0)   flags |= 8;
        }
        if (ua[0] & 0x0000FF00u)      flags |= 16;  // 1-byte mask signature
        if (ub[0] & 0x0000FF00u)      flags |= 32;
        #pragma unroll
        for (int off = 16; off > 0; off >>= 1)
            flags |= __shfl_xor_sync(0xffffffffu, flags, off);
    }
    const int swap = !(flags & 1);
    const void* tags = swap ? candB : candA;
    const void* mask = swap ? candA : candB;
    const int is32 = swap ? ((flags >> 3) & 1) : ((flags >> 2) & 1);
    const int is8  = swap ? ((flags >> 4) & 1) : ((flags >> 5) & 1);

    // ---------------- gold path score + length (all in registers) ----------
    float gall;
    int   len;
    {
        float gpart = 0.0f;
        int   lpart = 0;
        for (int t = lane; t < TT; t += NT) {
            if (get_mask(mask, b * TT + t, is8)) {
                lpart++;
                int tag  = get_tag(tags, b * TT + t, is32);
                int prev = (t == 0) ? START_TAG : get_tag(tags, b * TT + t - 1, is32);
                gpart += feats[t * FSTRIDE + b * LLAB + tag]
                       + trans[prev * LLAB + tag];
            }
        }
        #pragma unroll
        for (int off = 16; off > 0; off >>= 1) {
            gpart += __shfl_xor_sync(0xffffffffu, gpart, off);  // fixed order
            lpart += __shfl_xor_sync(0xffffffffu, lpart, off);
        }
        gall = gpart;
        len  = lpart;
    }
    len = len < 1 ? 1 : (len > TT ? TT : len);
    const int nsteps = len - 1;
    {
        int endid = get_tag(tags, b * TT + len - 1, is32);
        gall += trans[endid * LLAB + STOP_TAG];   // same in all lanes
    }

    // ---- per-lane packed E columns: Epk[i] = (E[i][j0], E[i][j0+1]) --------
    unsigned long long Epk[LLAB];
    #pragma unroll
    for (int i = 0; i < LLAB; ++i) {
        float e0 = expf(trans[i * LLAB + j0]);
        float e1 = expf(trans[i * LLAB + j0 + 1]);
        Epk[i] = pk2(e0, e1);
    }

    // ---------------- init: p_0 = f_0 + Tr[START][:] ------------------------
    const float* fb = feats + b * LLAB;
    float p00 = fb[0] + trans[START_TAG * LLAB + 0];
    if (act) {
        float pa = fb[j0]     + trans[START_TAG * LLAB + j0];
        float pb = fb[j0 + 1] + trans[START_TAG * LLAB + j0 + 1];
        float ua = ex2_approx((pa - p00) * L2E);
        float ub = ex2_approx((pb - p00) * L2E);
        ulonglong2 st; st.x = pk2(ua, ua); st.y = pk2(ub, ub);
        *reinterpret_cast<ulonglong2*>(&s_ud[0][j0]) = st;
    }
    float Cacc  = p00;
    float Clog2 = 0.0f;
    __syncwarp();

    // ---------------- feats prefetch (FIXED parity: slot 0 <- t=1) ----------
    float2 pf[2]; float pf0[2];
    {
        int t1 = (1 <= nsteps) ? 1 : (nsteps < 0 ? 0 : nsteps);
        int t2 = (2 <= nsteps) ? 2 : (nsteps < 0 ? 0 : nsteps);
        pf[0]  = *reinterpret_cast<const float2*>(fb + t1 * FSTRIDE + j0);
        pf0[0] = fb[t1 * FSTRIDE];
        pf[1]  = *reinterpret_cast<const float2*>(fb + t2 * FSTRIDE + j0);
        pf0[1] = fb[t2 * FSTRIDE];
    }

    const int npad = ((nsteps + RESC - 1) / RESC) * RESC;

    // tb always odd; step t=tb+k consumes slot k&1, reads buf k&1,
    // writes buf (k&1)^1 == t&1.
    for (int tb = 1; tb <= npad; tb += RESC) {
        #pragma unroll
        for (int k = 0; k < RESC; ++k) {
            const int  t    = tb + k;
            const bool live = (t <= nsteps);          // uniform across warp

            int tp = t + 2; if (tp > nsteps) tp = nsteps; if (tp < 0) tp = 0;
            float2 nf  = *reinterpret_cast<const float2*>(fb + tp * FSTRIDE + j0);
            float  nf0 = fb[tp * FSTRIDE];

            float f0 = pf0[k & 1];
            float e0 = ex2_approx((pf[k & 1].x - f0) * L2E);  // pre-sync
            float e1 = ex2_approx((pf[k & 1].y - f0) * L2E);
            unsigned long long epk = pk2(e0, e1);

            __syncwarp();                             // buf k&1 complete
            const unsigned long long* uin = s_ud[k & 1];

            float ru = 1.0f, lg = 0.0f;
            if (k == 0) {                             // rescale step
                float u0 = ((const float*)uin)[0];
                ru = rcp_approx(u0);
                lg = lg2_approx(u0);
            }

            // packed dot: 24 broadcast LDS.128 + 24 packed FMAs, 4 chains
            const ulonglong2* up = reinterpret_cast<const ulonglong2*>(uin);
            unsigned long long a0 = 0ULL, a1 = 0ULL, a2 = 0ULL, a3 = 0ULL;
            #pragma unroll
            for (int r = 0; r < 6; ++r) {
                ulonglong2 qa = up[4 * r + 0];   // dup(u_{8r}),   dup(u_{8r+1})
                ulonglong2 qb = up[4 * r + 1];
                ulonglong2 qc = up[4 * r + 2];
                ulonglong2 qd = up[4 * r + 3];
                asm("fma.rn.f32x2 %0, %1, %2, %0;" : "+l"(a0) : "l"(qa.x), "l"(Epk[8*r+0]));
                asm("fma.rn.f32x2 %0, %1, %2, %0;" : "+l"(a1) : "l"(qa.y), "l"(Epk[8*r+1]));
                asm("fma.rn.f32x2 %0, %1, %2, %0;" : "+l"(a2) : "l"(qb.x), "l"(Epk[8*r+2]));
                asm("fma.rn.f32x2 %0, %1, %2, %0;" : "+l"(a3) : "l"(qb.y), "l"(Epk[8*r+3]));
                asm("fma.rn.f32x2 %0, %1, %2, %0;" : "+l"(a0) : "l"(qc.x), "l"(Epk[8*r+4]));
                asm("fma.rn.f32x2 %0, %1, %2, %0;" : "+l"(a1) : "l"(qc.y), "l"(Epk[8*r+5]));
                asm("fma.rn.f32x2 %0, %1, %2, %0;" : "+l"(a2) : "l"(qd.x), "l"(Epk[8*r+6]));
                asm("fma.rn.f32x2 %0, %1, %2, %0;" : "+l"(a3) : "l"(qd.y), "l"(Epk[8*r+7]));
            }
            unsigned long long s01, s23, sp;
            asm("add.rn.f32x2 %0, %1, %2;" : "=l"(s01) : "l"(a0), "l"(a1));
            asm("add.rn.f32x2 %0, %1, %2;" : "=l"(s23) : "l"(a2), "l"(a3));
            asm("add.rn.f32x2 %0, %1, %2;" : "=l"(sp)  : "l"(s01), "l"(s23));

            // scale by packed (e0,e1) [and packed (ru,ru) on rescale steps]
            unsigned long long vpk;
            asm("mul.rn.f32x2 %0, %1, %2;" : "=l"(vpk) : "l"(sp), "l"(epk));
            if (k == 0) {
                unsigned long long rupk = pk2(ru, ru);
                asm("mul.rn.f32x2 %0, %1, %2;" : "=l"(vpk) : "l"(vpk), "l"(rupk));
            }

            // unpack once, duplicate, single STS.128
            float vlo, vhi;
            asm("mov.b64 {%0, %1}, %2;" : "=f"(vlo), "=f"(vhi) : "l"(vpk));
            if (act && live) {
                ulonglong2 st; st.x = pk2(vlo, vlo); st.y = pk2(vhi, vhi);
                *reinterpret_cast<ulonglong2*>(&s_ud[(k & 1) ^ 1][j0]) = st;
            }

            if (live) {                               // off critical path
                Cacc += f0;
                if (k == 0) Clog2 += lg;
            }
            pf[k & 1] = nf; pf0[k & 1] = nf0;
        }
    }
    __syncwarp();

    // -------- final transition to STOP: lane 23's Epk hi-halves = E[:,47] ---
    if (lane == 23) {
        const unsigned long long* uin = s_ud[nsteps & 1];
        const ulonglong2* up = reinterpret_cast<const ulonglong2*>(uin);
        unsigned long long a0 = 0ULL, a1 = 0ULL;
        #pragma unroll
        for (int m = 0; m < 24; ++m) {
            ulonglong2 q = up[m];
            asm("fma.rn.f32x2 %0, %1, %2, %0;" : "+l"(a0) : "l"(q.x), "l"(Epk[2*m]));
            asm("fma.rn.f32x2 %0, %1, %2, %0;" : "+l"(a1) : "l"(q.y), "l"(Epk[2*m+1]));
        }
        unsigned long long sp;
        asm("add.rn.f32x2 %0, %1, %2;" : "=l"(sp) : "l"(a0), "l"(a1));
        float slo, shi;
        asm("mov.b64 {%0, %1}, %2;" : "=f"(slo), "=f"(shi) : "l"(sp));
        float s = shi;   // state 47 = STOP column

        float fwd = Cacc + (Clog2 + lg2_approx(s)) * LN2f;
        g_partial[b] = fwd - gall;
        __threadfence();
        if (atomicInc(&g_done, BB - 1) == BB - 1) s_last = 1;
    }
    __syncwarp();

    // ---------------- last block: deterministic butterfly reduction ---------
    if (s_last) {
        float v = __ldcg(&g_partial[lane]) + __ldcg(&g_partial[lane + 32]);
        #pragma unroll
        for (int off = 16; off > 0; off >>= 1)
            v += __shfl_xor_sync(0xffffffffu, v, off);   // fixed order
        if (lane == 0) out[0] = v;
    }
}

extern "C" void kernel_launch(void* const* d_in, const int* in_sizes, int n_in,
                              void* d_out, int out_size) {
    const float* feats = nullptr;
    const float* trans = nullptr;
    const void*  candA = nullptr;
    const void*  candB = nullptr;
    for (int i = 0; i < n_in; ++i) {
        long long c = in_sizes[i];
        if      (c == (long long)TT * BB * LLAB) feats = (const float*)d_in[i];
        else if (c == (long long)LLAB * LLAB)    trans = (const float*)d_in[i];
        else if (!candA)                         candA = d_in[i];
        else                                     candB = d_in[i];
    }

    crf_fused_kernel<<<BB, NT>>>(feats, trans, candA, candB, (float*)d_out);
}